// round 14
// baseline (speedup 1.0000x reference)
#include <cuda_runtime.h>
#include <cuda_fp16.h>
#include <cstdint>

// ---------------------------------------------------------------------------
// TransformerXL relative position embedding — pure fp16 mma.sync m16n8k16.
// Prepass: Q/K -> fp16 pre-swizzled tile images + E build (one kernel).
// Main: one cp.async group, 2 barriers, fused gemm stretch.
//
// out[b,n,u,w,c] = AC[w,c] + (0 <= c-w < 128 ? BD[w, c-w] : 0)
// ---------------------------------------------------------------------------

namespace {
constexpr int Uu = 32, Nn = 8, Cc = 255;

// main-kernel smem (bytes)
constexpr int OFF_A_B  = 0;          // sA : 64 rows  x 128B (Q half)      8 KB
constexpr int OFF_E_B  = 8192;       // sE : 128 rows x 128B (E)          16 KB
constexpr int OFF_B0_B = 24576;      // sB0: 128 rows x 128B (K half 0)   16 KB
constexpr int OFF_B1_B = 40960;      // sB1: 128 rows x 128B (K half 1)   16 KB
constexpr int OFF_BD_B = 57344;      // sBD: 64 x 137 halfs             17.1 KB
constexpr int BDS_H = 137;
constexpr int SMEM_BYTES = OFF_BD_B + 64 * BDS_H * 2;   // 74880 -> 3 CTAs/SM

constexpr int NQ_CHUNKS = 128 * 8 * 128 * 8;   // Q image chunks
constexpr int NK_CHUNKS = 128 * 8 * 256 * 8;   // K image chunks
constexpr int CONV_BLOCKS = 3072;
}

// fp16 pre-swizzled tile images (16B chunks)
__device__ uint4 g_Qh[128 * 8 * 128 * 8];   // [(b,u)][n][w][8]   16 MB
__device__ uint4 g_Kh[128 * 8 * 256 * 8];   // [(b,u)][n][c][8]   32 MB (c=255 zero)
__device__ uint4 g_Epk[8 * 128 * 8];        // [n][f][8]          128 KB

// ---------------------------------------------------------------------------
__device__ __forceinline__ void mma16(float* c, const uint32_t* a, const uint32_t* b) {
    asm volatile(
        "mma.sync.aligned.m16n8k16.row.col.f32.f16.f16.f32 "
        "{%0,%1,%2,%3}, {%4,%5,%6,%7}, {%8,%9}, {%0,%1,%2,%3};"
        : "+f"(c[0]), "+f"(c[1]), "+f"(c[2]), "+f"(c[3])
        : "r"(a[0]), "r"(a[1]), "r"(a[2]), "r"(a[3]), "r"(b[0]), "r"(b[1]));
}

#define LDSM_X4(r, addr)                                                        \
    asm volatile("ldmatrix.sync.aligned.m8n8.x4.shared.b16 {%0,%1,%2,%3}, [%4];"\
                 : "=r"((r)[0]), "=r"((r)[1]), "=r"((r)[2]), "=r"((r)[3])       \
                 : "r"(addr))

__device__ __forceinline__ uint32_t pack_h2(float a, float b) {
    __half2 h = __floats2half2_rn(a, b);
    return *reinterpret_cast<uint32_t*>(&h);
}

__device__ __forceinline__ uint4 pack_quad(float4 v0, float4 v1) {
    uint4 r;
    r.x = pack_h2(v0.x, v0.y);
    r.y = pack_h2(v0.z, v0.w);
    r.z = pack_h2(v1.x, v1.y);
    r.w = pack_h2(v1.z, v1.w);
    return r;
}

__device__ __forceinline__ void cp16(uint32_t dst, const void* src) {
    asm volatile("cp.async.ca.shared.global [%0], [%1], 16;" :: "r"(dst), "l"(src));
}

// 32x32 warp-tile gemm over K=64 via ldmatrix (validated R11-R13).
__device__ __forceinline__ void gemm_warp(uint32_t sAu, uint32_t sBu,
                                          float acc[2][4][4],
                                          int rm, int cn, int lane) {
    const int la = lane & 15;
    const int ca = lane >> 4;
    const int lb = (lane & 7) | ((lane >> 4) << 3);
    const int cb = (lane >> 3) & 1;
    const uint32_t aB0 = sAu + (uint32_t)(rm + la) * 128;
    const uint32_t aB1 = aB0 + 16 * 128;
    const uint32_t bB0 = sBu + (uint32_t)(cn + lb) * 128;
    const uint32_t bB1 = bB0 + 16 * 128;
    const int swA = (rm + la) & 7;
    const int swB = (cn + lb) & 7;
    #pragma unroll
    for (int kb = 0; kb < 4; ++kb) {
        uint32_t a0[4], a1[4], b0[4], b1[4];
        LDSM_X4(a0, aB0 + (uint32_t)(((2 * kb + ca) ^ swA) << 4));
        LDSM_X4(a1, aB1 + (uint32_t)(((2 * kb + ca) ^ swA) << 4));
        LDSM_X4(b0, bB0 + (uint32_t)(((2 * kb + cb) ^ swB) << 4));
        LDSM_X4(b1, bB1 + (uint32_t)(((2 * kb + cb) ^ swB) << 4));
        mma16(acc[0][0], a0, b0);      mma16(acc[1][0], a1, b0);
        mma16(acc[0][1], a0, b0 + 2);  mma16(acc[1][1], a1, b0 + 2);
        mma16(acc[0][2], a0, b1);      mma16(acc[1][2], a1, b1);
        mma16(acc[0][3], a0, b1 + 2);  mma16(acc[1][3], a1, b1 + 2);
    }
}

// ---------------------------------------------------------------------------
// Prepass (merged): blocks [0,3072) convert Q/K; blocks [3072,3200) build E.
// 256 threads everywhere.
// ---------------------------------------------------------------------------
__global__ __launch_bounds__(256)
void prepass_kernel(const float* __restrict__ q, const float* __restrict__ k,
                    const float* __restrict__ pk) {
    const int blk = blockIdx.x;
    const int tid = threadIdx.x;

    if (blk < CONV_BLOCKS) {
        for (int idx = blk * 256 + tid; idx < NQ_CHUNKS + NK_CHUNKS;
             idx += CONV_BLOCKS * 256) {
            if (idx < NQ_CHUNKS) {
                const int c8 = idx & 7, w = (idx >> 3) & 127;
                const int n = (idx >> 10) & 7, bu = idx >> 13;
                const float* s = q + (size_t)bu * 65536 + w * 512 + n * 64 + c8 * 8;
                float4 v0 = *(const float4*)s;
                float4 v1 = *(const float4*)(s + 4);
                g_Qh[(size_t)((bu * 8 + n) * 128 + w) * 8 + (c8 ^ (w & 7))] =
                    pack_quad(v0, v1);
            } else {
                const int j = idx - NQ_CHUNKS;
                const int c8 = j & 7, c = (j >> 3) & 255;
                const int n = (j >> 11) & 7, bu = j >> 14;
                uint4 r = make_uint4(0u, 0u, 0u, 0u);
                if (c < Cc) {
                    const float* s = k + (size_t)bu * (Cc * 512) + (size_t)c * 512
                                     + n * 64 + c8 * 8;
                    float4 v0 = *(const float4*)s;
                    float4 v1 = *(const float4*)(s + 4);
                    r = pack_quad(v0, v1);
                }
                g_Kh[(size_t)((bu * 8 + n) * 256 + c) * 8 + (c8 ^ (c & 7))] = r;
            }
        }
        return;
    }

    // ---- E blocks: bid_e = (fg [0,64) , nhh [0,2)) ----
    __shared__ float sig[2 * 512];
    __shared__ float sp[4 * 2 * 256];

    const int bid_e = blk - CONV_BLOCKS;
    const int fg  = bid_e & 63;
    const int nhh = bid_e >> 6;
    const int f2  = fg * 2;
    const int nh0 = nhh * 256;
    const float log_inc = 9.210340371976184f / 255.0f;

    #pragma unroll
    for (int i = 0; i < 4; ++i) {
        int tt = tid + 256 * i;
        int fi = tt >> 9, d = tt & 511, j = d & 255;
        float arg = (float)(127 - (f2 + fi)) * expf(-(float)j * log_inc);
        sig[fi * 512 + d] = (d < 256) ? sinf(arg) : cosf(arg);
    }
    __syncthreads();

    const int qq = tid & 63, ch = tid >> 6;        // 4 chunks x 128 d
    const float* p = pk + (size_t)(ch * 128) * 512 + nh0 + 4 * qq;
    float4 a0 = make_float4(0.f, 0.f, 0.f, 0.f);
    float4 a1 = make_float4(0.f, 0.f, 0.f, 0.f);
    #pragma unroll 4
    for (int dd = 0; dd < 128; ++dd) {
        float4 v = __ldg((const float4*)(p + (size_t)dd * 512));
        int d = ch * 128 + dd;
        float s0 = sig[d], s1 = sig[512 + d];
        a0.x = fmaf(s0, v.x, a0.x); a0.y = fmaf(s0, v.y, a0.y);
        a0.z = fmaf(s0, v.z, a0.z); a0.w = fmaf(s0, v.w, a0.w);
        a1.x = fmaf(s1, v.x, a1.x); a1.y = fmaf(s1, v.y, a1.y);
        a1.z = fmaf(s1, v.z, a1.z); a1.w = fmaf(s1, v.w, a1.w);
    }
    *(float4*)&sp[(ch * 2 + 0) * 256 + 4 * qq] = a0;
    *(float4*)&sp[(ch * 2 + 1) * 256 + 4 * qq] = a1;
    __syncthreads();

    if (tid < 128) {
        int fi = tid >> 6, q64 = tid & 63;
        float4 s = make_float4(0.f, 0.f, 0.f, 0.f);
        #pragma unroll
        for (int c = 0; c < 4; ++c) {
            float4 v = *(const float4*)&sp[(c * 2 + fi) * 256 + 4 * q64];
            s.x += v.x; s.y += v.y; s.z += v.z; s.w += v.w;
        }
        const int n   = nhh * 4 + (q64 >> 4);
        const int h4  = (4 * q64) & 63;              // multiple of 4
        const int row = f2 + fi;
        const int chv = h4 >> 3;
        uint32_t* dst = reinterpret_cast<uint32_t*>(g_Epk)
                        + n * (128 * 32) + row * 32
                        + ((chv ^ (row & 7)) << 2) + ((h4 & 7) >> 1);
        dst[0] = pack_h2(s.x, s.y);
        dst[1] = pack_h2(s.z, s.w);
    }
}

// ---------------------------------------------------------------------------
// Main kernel: one CTA per (b,u,n,mh), 256 threads (8 warps, 2m x 4n).
// bid layout: [b:2][u:5][n:3][mh:1].  Two barriers total.
// ---------------------------------------------------------------------------
__device__ __forceinline__ void epilogue(const float acc[2][4][4],
                                         const __half* __restrict__ sBD,
                                         float* __restrict__ OUT,
                                         int half, int mh,
                                         int wm, int wn, int g, int t) {
    #pragma unroll
    for (int i = 0; i < 2; ++i)
        #pragma unroll
        for (int j = 0; j < 4; ++j) {
            const int c0 = 128 * half + 32 * wn + 8 * j + 2 * t;
            #pragma unroll
            for (int p = 0; p < 2; ++p) {
                const int lw = 32 * wm + 16 * i + g + 8 * p;
                const int wg = mh * 64 + lw;
                float v0 = acc[i][j][2 * p];
                float v1 = acc[i][j][2 * p + 1];
                const int f = c0 - wg;
                if (f >= 0 && f < 127) {
                    __half2 h = *reinterpret_cast<const __half2*>(&sBD[lw * BDS_H + f]);
                    float2 bd = __half22float2(h);
                    v0 += bd.x; v1 += bd.y;
                } else if (f == -1) {
                    v1 += __half2float(sBD[lw * BDS_H]);
                } else if (f == 127) {
                    v0 += __half2float(sBD[lw * BDS_H + 127]);
                }
                float* o = &OUT[(size_t)lw * Cc + c0];
                o[0] = v0;
                if (c0 + 1 < Cc) o[1] = v1;
            }
        }
}

__global__ __launch_bounds__(256, 3)
void txl_mma_kernel(float* __restrict__ out_g) {
    extern __shared__ uint32_t sm[];
    uint32_t smem_base;
    asm("{ .reg .u64 t; cvta.to.shared.u64 t, %1; cvt.u32.u64 %0, t; }"
        : "=r"(smem_base) : "l"(sm));
    const uint32_t sAu  = smem_base + OFF_A_B;
    const uint32_t sEu  = smem_base + OFF_E_B;
    const uint32_t sB0u = smem_base + OFF_B0_B;
    const uint32_t sB1u = smem_base + OFF_B1_B;
    __half* sBD = reinterpret_cast<__half*>(reinterpret_cast<char*>(sm) + OFF_BD_B);

    const int tid = threadIdx.x;
    const int lane = tid & 31, wid = tid >> 5;
    const int wm = wid & 1, wn = wid >> 1;
    const int g = lane >> 2, t = lane & 3;

    const int bid = blockIdx.x;
    const int mh = bid & 1;
    const int n = (bid >> 1) & 7;
    const int u = (bid >> 4) & 31;
    const int b = bid >> 9;
    const int bu = b * Uu + u;

    float* OUT = out_g + ((size_t)((b * Nn + n) * Uu + u) * 128 + (size_t)mh * 64) * Cc;

    // ---- issue ALL tile loads at t0, one cp.async group ----
    const uint4* Qv = g_Qh + (size_t)((bu * 8 + n) * 128 + mh * 64) * 8;
    const uint4* Ev = g_Epk + (size_t)n * (128 * 8);
    const uint4* Kv = g_Kh + (size_t)(bu * 8 + n) * 256 * 8;

    #pragma unroll
    for (int i = 0; i < 2; ++i)
        cp16(sAu + (uint32_t)(tid + 256 * i) * 16, Qv + tid + 256 * i);
    #pragma unroll
    for (int i = 0; i < 4; ++i)
        cp16(sEu + (uint32_t)(tid + 256 * i) * 16, Ev + tid + 256 * i);
    #pragma unroll
    for (int i = 0; i < 4; ++i)
        cp16(sB0u + (uint32_t)(tid + 256 * i) * 16, Kv + tid + 256 * i);
    #pragma unroll
    for (int i = 0; i < 4; ++i)
        cp16(sB1u + (uint32_t)(tid + 256 * i) * 16, Kv + 1024 + tid + 256 * i);
    asm volatile("cp.async.commit_group;");
    asm volatile("cp.async.wait_group 0;");
    __syncthreads();                                   // barrier #1

    float acc[2][4][4];

    // ---- BD = Q @ E^T -> stage to sBD (fp16) ----
    #pragma unroll
    for (int i = 0; i < 2; ++i)
        #pragma unroll
        for (int j = 0; j < 4; ++j)
            #pragma unroll
            for (int e = 0; e < 4; ++e) acc[i][j][e] = 0.f;
    gemm_warp(sAu, sEu, acc, 32 * wm, 32 * wn, lane);
    #pragma unroll
    for (int i = 0; i < 2; ++i)
        #pragma unroll
        for (int j = 0; j < 4; ++j) {
            const int w0 = 32 * wm + 16 * i + g;
            const int f0 = 32 * wn + 8 * j + 2 * t;
            sBD[w0 * BDS_H + f0]           = __float2half_rn(acc[i][j][0]);
            sBD[w0 * BDS_H + f0 + 1]       = __float2half_rn(acc[i][j][1]);
            sBD[(w0 + 8) * BDS_H + f0]     = __float2half_rn(acc[i][j][2]);
            sBD[(w0 + 8) * BDS_H + f0 + 1] = __float2half_rn(acc[i][j][3]);
        }

    // ---- AC0 gemm immediately (no barrier; sB0 covered by barrier #1) ----
    #pragma unroll
    for (int i = 0; i < 2; ++i)
        #pragma unroll
        for (int j = 0; j < 4; ++j)
            #pragma unroll
            for (int e = 0; e < 4; ++e) acc[i][j][e] = 0.f;
    gemm_warp(sAu, sB0u, acc, 32 * wm, 32 * wn, lane);

    __syncthreads();                                   // barrier #2: publish sBD

    // ---- epi0, then AC1 gemm, then epi1 ----
    epilogue(acc, sBD, OUT, 0, mh, wm, wn, g, t);

    #pragma unroll
    for (int i = 0; i < 2; ++i)
        #pragma unroll
        for (int j = 0; j < 4; ++j)
            #pragma unroll
            for (int e = 0; e < 4; ++e) acc[i][j][e] = 0.f;
    gemm_warp(sAu, sB1u, acc, 32 * wm, 32 * wn, lane);

    epilogue(acc, sBD, OUT, 1, mh, wm, wn, g, t);
}

// ---------------------------------------------------------------------------
extern "C" void kernel_launch(void* const* d_in, const int* in_sizes, int n_in,
                              void* d_out, int out_size) {
    (void)in_sizes; (void)n_in; (void)out_size;
    const float* q  = (const float*)d_in[0];   // queries (4,32,128,8,64)
    const float* k  = (const float*)d_in[1];   // keys    (4,32,255,8,64)
    const float* pk = (const float*)d_in[2];   // pos_kernel (512,8,64)
    float* out = (float*)d_out;                // (4,8,32,128,255)

    prepass_kernel<<<CONV_BLOCKS + 128, 256>>>(q, k, pk);

    cudaFuncSetAttribute(txl_mma_kernel,
                         cudaFuncAttributeMaxDynamicSharedMemorySize, SMEM_BYTES);
    txl_mma_kernel<<<2 * 4 * Uu * Nn, 256, SMEM_BYTES>>>(out);
}

// round 15
// speedup vs baseline: 1.3778x; 1.3778x over previous
#include <cuda_runtime.h>
#include <cuda_fp16.h>
#include <cstdint>

// ---------------------------------------------------------------------------
// TransformerXL relative position embedding — pure fp16 mma.sync m16n8k16.
// In-kernel Q/K fp16 packing, fused phases, swizzled smem output staging.
//   q·k ≈ qh·kh  (fp16 operands, fp32 accum; rel_err ~3e-4)
//
// out[b,n,u,w,c] = AC[w,c] + (0 <= c-w < 128 ? BD[w, c-w] : 0)
// ---------------------------------------------------------------------------

namespace {
constexpr int Uu = 32, Nn = 8, Cc = 255;

// smem layout (bytes)
constexpr int OFF_A_B  = 0;          // sA : 64 rows  x 128B (Q half)      8 KB
constexpr int OFF_E_B  = 8192;       // sE : 128 rows x 128B (E)          16 KB
constexpr int OFF_B0_B = 24576;      // sB0: 128 rows x 128B (K half 0)   16 KB
constexpr int OFF_B1_B = 40960;      // sB1: 128 rows x 128B (K half 1)   16 KB
constexpr int OFF_BD_B = 57344;      // sBD: 64 x 137 halfs             17.1 KB
constexpr int BDS_H = 137;
constexpr int SMEM_BYTES = OFF_BD_B + 64 * BDS_H * 2;   // 74880 -> 3 CTAs/SM
// output stage: 64 rows x 128 fp32, XOR-swizzled, REUSES sE+sB0 (exactly 32 KB)
}

// E image, fp16, chunk-swizzled: [n][f][8 x 16B chunks] = 128 KB
__device__ uint4 g_Epk[8 * 128 * 8];

// ---------------------------------------------------------------------------
__device__ __forceinline__ void mma16(float* c, const uint32_t* a, const uint32_t* b) {
    asm volatile(
        "mma.sync.aligned.m16n8k16.row.col.f32.f16.f16.f32 "
        "{%0,%1,%2,%3}, {%4,%5,%6,%7}, {%8,%9}, {%0,%1,%2,%3};"
        : "+f"(c[0]), "+f"(c[1]), "+f"(c[2]), "+f"(c[3])
        : "r"(a[0]), "r"(a[1]), "r"(a[2]), "r"(a[3]), "r"(b[0]), "r"(b[1]));
}

#define LDSM_X4(r, addr)                                                        \
    asm volatile("ldmatrix.sync.aligned.m8n8.x4.shared.b16 {%0,%1,%2,%3}, [%4];"\
                 : "=r"((r)[0]), "=r"((r)[1]), "=r"((r)[2]), "=r"((r)[3])       \
                 : "r"(addr))

__device__ __forceinline__ uint32_t pack_h2(float a, float b) {
    __half2 h = __floats2half2_rn(a, b);
    return *reinterpret_cast<uint32_t*>(&h);
}

__device__ __forceinline__ uint4 pack_quad(float4 v0, float4 v1) {
    uint4 r;
    r.x = pack_h2(v0.x, v0.y);
    r.y = pack_h2(v0.z, v0.w);
    r.z = pack_h2(v1.x, v1.y);
    r.w = pack_h2(v1.z, v1.w);
    return r;
}

__device__ __forceinline__ void cp16(uint32_t dst, const void* src) {
    asm volatile("cp.async.ca.shared.global [%0], [%1], 16;" :: "r"(dst), "l"(src));
}

// 32x32 warp-tile gemm over K=64 via ldmatrix (validated R11-R14).
__device__ __forceinline__ void gemm_warp(uint32_t sAu, uint32_t sBu,
                                          float acc[2][4][4],
                                          int rm, int cn, int lane) {
    const int la = lane & 15;
    const int ca = lane >> 4;
    const int lb = (lane & 7) | ((lane >> 4) << 3);
    const int cb = (lane >> 3) & 1;
    const uint32_t aB0 = sAu + (uint32_t)(rm + la) * 128;
    const uint32_t aB1 = aB0 + 16 * 128;
    const uint32_t bB0 = sBu + (uint32_t)(cn + lb) * 128;
    const uint32_t bB1 = bB0 + 16 * 128;
    const int swA = (rm + la) & 7;
    const int swB = (cn + lb) & 7;
    #pragma unroll
    for (int kb = 0; kb < 4; ++kb) {
        uint32_t a0[4], a1[4], b0[4], b1[4];
        LDSM_X4(a0, aB0 + (uint32_t)(((2 * kb + ca) ^ swA) << 4));
        LDSM_X4(a1, aB1 + (uint32_t)(((2 * kb + ca) ^ swA) << 4));
        LDSM_X4(b0, bB0 + (uint32_t)(((2 * kb + cb) ^ swB) << 4));
        LDSM_X4(b1, bB1 + (uint32_t)(((2 * kb + cb) ^ swB) << 4));
        mma16(acc[0][0], a0, b0);      mma16(acc[1][0], a1, b0);
        mma16(acc[0][1], a0, b0 + 2);  mma16(acc[1][1], a1, b0 + 2);
        mma16(acc[0][2], a0, b1);      mma16(acc[1][2], a1, b1);
        mma16(acc[0][3], a0, b1 + 2);  mma16(acc[1][3], a1, b1 + 2);
    }
}

// ---------------------------------------------------------------------------
// E prepass: E[f][nh] = sum_d sig(f,d)*pk[d][nh], fp16 swizzled image.
// grid 128 = (64 f-pairs) x (2 nh-halves), 1024 threads. (validated R13)
// ---------------------------------------------------------------------------
__global__ __launch_bounds__(1024)
void compute_E_kernel(const float* __restrict__ pk) {
    __shared__ float sig[2 * 512];
    __shared__ float sp[16 * 2 * 256];

    const int fg  = blockIdx.x & 63;
    const int nhh = blockIdx.x >> 6;
    const int f2  = fg * 2;
    const int nh0 = nhh * 256;
    const int tid = threadIdx.x;
    const float log_inc = 9.210340371976184f / 255.0f;

    {
        int fi = tid >> 9, d = tid & 511, j = d & 255;
        float arg = (float)(127 - (f2 + fi)) * expf(-(float)j * log_inc);
        sig[fi * 512 + d] = (d < 256) ? sinf(arg) : cosf(arg);
    }
    __syncthreads();

    const int q = tid & 63, ch = tid >> 6;
    const float* p = pk + (size_t)(ch * 32) * 512 + nh0 + 4 * q;
    float4 a0 = make_float4(0.f, 0.f, 0.f, 0.f);
    float4 a1 = make_float4(0.f, 0.f, 0.f, 0.f);
    #pragma unroll
    for (int dd = 0; dd < 32; ++dd) {
        float4 v = __ldg((const float4*)(p + (size_t)dd * 512));
        int d = ch * 32 + dd;
        float s0 = sig[d], s1 = sig[512 + d];
        a0.x = fmaf(s0, v.x, a0.x); a0.y = fmaf(s0, v.y, a0.y);
        a0.z = fmaf(s0, v.z, a0.z); a0.w = fmaf(s0, v.w, a0.w);
        a1.x = fmaf(s1, v.x, a1.x); a1.y = fmaf(s1, v.y, a1.y);
        a1.z = fmaf(s1, v.z, a1.z); a1.w = fmaf(s1, v.w, a1.w);
    }
    *(float4*)&sp[(ch * 2 + 0) * 256 + 4 * q] = a0;
    *(float4*)&sp[(ch * 2 + 1) * 256 + 4 * q] = a1;
    __syncthreads();

    if (tid < 128) {
        int fi = tid >> 6, qq = tid & 63;
        float4 s = make_float4(0.f, 0.f, 0.f, 0.f);
        #pragma unroll
        for (int c = 0; c < 16; ++c) {
            float4 v = *(const float4*)&sp[(c * 2 + fi) * 256 + 4 * qq];
            s.x += v.x; s.y += v.y; s.z += v.z; s.w += v.w;
        }
        const int n   = nhh * 4 + (qq >> 4);
        const int h4  = (4 * qq) & 63;
        const int row = f2 + fi;
        const int chv = h4 >> 3;
        uint32_t* dst = reinterpret_cast<uint32_t*>(g_Epk)
                        + n * (128 * 32) + row * 32
                        + ((chv ^ (row & 7)) << 2) + ((h4 & 7) >> 1);
        dst[0] = pack_h2(s.x, s.y);
        dst[1] = pack_h2(s.z, s.w);
    }
}

// ---------------------------------------------------------------------------
// Main kernel: one CTA per (b,u,n,mh), 256 threads (8 warps, 2m x 4n).
// bid layout: [b:2][u:5][n:3][mh:1].
// ---------------------------------------------------------------------------
__device__ __forceinline__ void epi_stage(const float acc[2][4][4],
                                          const __half* __restrict__ sBD,
                                          float* __restrict__ stage,
                                          int half, int mh,
                                          int wm, int wn, int g, int t) {
    #pragma unroll
    for (int i = 0; i < 2; ++i)
        #pragma unroll
        for (int j = 0; j < 4; ++j) {
            const int lc = 32 * wn + 8 * j + 2 * t;       // stage col
            const int c0 = 128 * half + lc;               // global col
            #pragma unroll
            for (int p = 0; p < 2; ++p) {
                const int lw = 32 * wm + 16 * i + g + 8 * p;
                const int wg = mh * 64 + lw;
                float v0 = acc[i][j][2 * p];
                float v1 = acc[i][j][2 * p + 1];
                const int f = c0 - wg;
                if (f >= 0 && f < 127) {
                    __half2 h = *reinterpret_cast<const __half2*>(&sBD[lw * BDS_H + f]);
                    float2 bd = __half22float2(h);
                    v0 += bd.x; v1 += bd.y;
                } else if (f == -1) {
                    v1 += __half2float(sBD[lw * BDS_H]);
                } else if (f == 127) {
                    v0 += __half2float(sBD[lw * BDS_H + 127]);
                }
                // swizzled stage store: sw(r) = (8r)&127 (bits 3..6, disjoint
                // from t-bits 1..2 -> conflict-free per phase)
                const int sw = (8 * lw) & 127;
                *(float2*)&stage[lw * 128 + (lc ^ sw)] = make_float2(v0, v1);
            }
        }
}

__device__ __forceinline__ void copy_stage(const float* __restrict__ stage,
                                           float* __restrict__ OUT,
                                           int half, int tid) {
    #pragma unroll 8
    for (int i = 0; i < 32; ++i) {
        const int flat = tid + 256 * i;                   // 64*128
        const int r = flat >> 7, c = flat & 127;
        const float v = stage[r * 128 + (c ^ ((8 * r) & 127))];
        const int gc = 128 * half + c;
        if (gc < Cc) OUT[(size_t)r * Cc + gc] = v;
    }
}

__global__ __launch_bounds__(256, 3)
void txl_mma_kernel(const float* __restrict__ q_g,
                    const float* __restrict__ k_g,
                    float* __restrict__ out_g) {
    extern __shared__ uint32_t sm[];
    uint32_t smem_base;
    asm("{ .reg .u64 t; cvta.to.shared.u64 t, %1; cvt.u32.u64 %0, t; }"
        : "=r"(smem_base) : "l"(sm));
    const uint32_t sAu  = smem_base + OFF_A_B;
    const uint32_t sEu  = smem_base + OFF_E_B;
    const uint32_t sB0u = smem_base + OFF_B0_B;
    const uint32_t sB1u = smem_base + OFF_B1_B;
    char* sbytes = reinterpret_cast<char*>(sm);
    __half* sBD  = reinterpret_cast<__half*>(sbytes + OFF_BD_B);
    float* stage = reinterpret_cast<float*>(sbytes + OFF_E_B);   // reuses sE+sB0

    const int tid = threadIdx.x;
    const int lane = tid & 31, wid = tid >> 5;
    const int wm = wid & 1, wn = wid >> 1;
    const int g = lane >> 2, t = lane & 3;

    const int bid = blockIdx.x;
    const int mh = bid & 1;
    const int n = (bid >> 1) & 7;
    const int u = (bid >> 4) & 31;
    const int b = bid >> 9;

    const float* Q  = q_g + (size_t)(b * Uu + u) * 128 * 512 + (size_t)mh * 64 * 512 + n * 64;
    const float* Kg = k_g + (size_t)(b * Uu + u) * Cc * 512 + n * 64;
    float* OUT = out_g + ((size_t)((b * Nn + n) * Uu + u) * 128 + (size_t)mh * 64) * Cc;

    // pack-task decode
    const int t_row0 = tid >> 3;                 // 0..31
    const int t_c    = tid & 7;                  // 16B chunk
    const int t_sc   = t_c ^ (t_row0 & 7);       // swizzled chunk (rows step by 32)
    const int t_hb   = t_c * 8;

    // ---- phase 1: E cp.async + pack Q, K0, K1 (one long stretch) ----
    {
        const uint4* Ev = g_Epk + (size_t)n * (128 * 8);
        #pragma unroll
        for (int i = 0; i < 4; ++i)
            cp16(sEu + (uint32_t)(tid + 256 * i) * 16, Ev + tid + 256 * i);
        asm volatile("cp.async.commit_group;");
    }
    #pragma unroll
    for (int it = 0; it < 2; ++it) {             // Q: 64 rows
        const int row = t_row0 + 32 * it;
        float4 v0 = *(const float4*)&Q[(size_t)row * 512 + t_hb];
        float4 v1 = *(const float4*)&Q[(size_t)row * 512 + t_hb + 4];
        *(uint4*)(sbytes + OFF_A_B + row * 128 + t_sc * 16) = pack_quad(v0, v1);
    }
    #pragma unroll
    for (int it = 0; it < 4; ++it) {             // K rows 0..127 -> sB0
        const int row = t_row0 + 32 * it;
        float4 v0 = *(const float4*)&Kg[(size_t)row * 512 + t_hb];
        float4 v1 = *(const float4*)&Kg[(size_t)row * 512 + t_hb + 4];
        *(uint4*)(sbytes + OFF_B0_B + row * 128 + t_sc * 16) = pack_quad(v0, v1);
    }
    #pragma unroll
    for (int it = 0; it < 4; ++it) {             // K rows 128..255 -> sB1
        const int row = 128 + t_row0 + 32 * it;
        float4 z = make_float4(0.f, 0.f, 0.f, 0.f);
        float4 v0 = (row < Cc) ? *(const float4*)&Kg[(size_t)row * 512 + t_hb] : z;
        float4 v1 = (row < Cc) ? *(const float4*)&Kg[(size_t)row * 512 + t_hb + 4] : z;
        *(uint4*)(sbytes + OFF_B1_B + (row - 128) * 128 + t_sc * 16) = pack_quad(v0, v1);
    }
    asm volatile("cp.async.wait_group 0;");
    __syncthreads();                              // barrier 1

    float acc[2][4][4];

    // ---- BD = Q @ E^T -> sBD; AC0 gemm (no barrier between) ----
    #pragma unroll
    for (int i = 0; i < 2; ++i)
        #pragma unroll
        for (int j = 0; j < 4; ++j)
            #pragma unroll
            for (int e = 0; e < 4; ++e) acc[i][j][e] = 0.f;
    gemm_warp(sAu, sEu, acc, 32 * wm, 32 * wn, lane);
    #pragma unroll
    for (int i = 0; i < 2; ++i)
        #pragma unroll
        for (int j = 0; j < 4; ++j) {
            const int w0 = 32 * wm + 16 * i + g;
            const int f0 = 32 * wn + 8 * j + 2 * t;
            sBD[w0 * BDS_H + f0]           = __float2half_rn(acc[i][j][0]);
            sBD[w0 * BDS_H + f0 + 1]       = __float2half_rn(acc[i][j][1]);
            sBD[(w0 + 8) * BDS_H + f0]     = __float2half_rn(acc[i][j][2]);
            sBD[(w0 + 8) * BDS_H + f0 + 1] = __float2half_rn(acc[i][j][3]);
        }

    #pragma unroll
    for (int i = 0; i < 2; ++i)
        #pragma unroll
        for (int j = 0; j < 4; ++j)
            #pragma unroll
            for (int e = 0; e < 4; ++e) acc[i][j][e] = 0.f;
    gemm_warp(sAu, sB0u, acc, 32 * wm, 32 * wn, lane);

    __syncthreads();                              // barrier 2: sBD published; sE/sB0 dead

    epi_stage(acc, sBD, stage, 0, mh, wm, wn, g, t);
    __syncthreads();                              // barrier 3: stage0 complete

    // AC1 gemm + coalesced copy of stage0
    #pragma unroll
    for (int i = 0; i < 2; ++i)
        #pragma unroll
        for (int j = 0; j < 4; ++j)
            #pragma unroll
            for (int e = 0; e < 4; ++e) acc[i][j][e] = 0.f;
    copy_stage(stage, OUT, 0, tid);
    gemm_warp(sAu, sB1u, acc, 32 * wm, 32 * wn, lane);

    __syncthreads();                              // barrier 4: stage reads done

    epi_stage(acc, sBD, stage, 1, mh, wm, wn, g, t);
    __syncthreads();                              // barrier 5
    copy_stage(stage, OUT, 1, tid);
}

// ---------------------------------------------------------------------------
extern "C" void kernel_launch(void* const* d_in, const int* in_sizes, int n_in,
                              void* d_out, int out_size) {
    (void)in_sizes; (void)n_in; (void)out_size;
    const float* q  = (const float*)d_in[0];   // queries (4,32,128,8,64)
    const float* k  = (const float*)d_in[1];   // keys    (4,32,255,8,64)
    const float* pk = (const float*)d_in[2];   // pos_kernel (512,8,64)
    float* out = (float*)d_out;                // (4,8,32,128,255)

    compute_E_kernel<<<128, 1024>>>(pk);

    cudaFuncSetAttribute(txl_mma_kernel,
                         cudaFuncAttributeMaxDynamicSharedMemorySize, SMEM_BYTES);
    txl_mma_kernel<<<2 * 4 * Uu * Nn, 256, SMEM_BYTES>>>(q, k, out);
}

// round 16
// speedup vs baseline: 1.3854x; 1.0055x over previous
#include <cuda_runtime.h>
#include <cuda_fp16.h>
#include <cstdint>

// ---------------------------------------------------------------------------
// TransformerXL relative position embedding — pure fp16 mma.sync m16n8k16.
// In-kernel Q/K fp16 packing + fused 2-barrier phase structure + direct stores.
//   q·k ≈ qh·kh  (fp16 operands, fp32 accum; rel_err ~3e-4)
//
// out[b,n,u,w,c] = AC[w,c] + (0 <= c-w < 128 ? BD[w, c-w] : 0)
// ---------------------------------------------------------------------------

namespace {
constexpr int Uu = 32, Nn = 8, Cc = 255;

// smem layout (bytes)
constexpr int OFF_A_B  = 0;          // sA : 64 rows  x 128B (Q half)      8 KB
constexpr int OFF_E_B  = 8192;       // sE : 128 rows x 128B (E)          16 KB
constexpr int OFF_B0_B = 24576;      // sB0: 128 rows x 128B (K half 0)   16 KB
constexpr int OFF_B1_B = 40960;      // sB1: 128 rows x 128B (K half 1)   16 KB
constexpr int OFF_BD_B = 57344;      // sBD: 64 x 137 halfs             17.1 KB
constexpr int BDS_H = 137;
constexpr int SMEM_BYTES = OFF_BD_B + 64 * BDS_H * 2;   // 74880 -> 3 CTAs/SM
}

// E image, fp16, chunk-swizzled: [n][f][8 x 16B chunks] = 128 KB
__device__ uint4 g_Epk[8 * 128 * 8];

// ---------------------------------------------------------------------------
__device__ __forceinline__ void mma16(float* c, const uint32_t* a, const uint32_t* b) {
    asm volatile(
        "mma.sync.aligned.m16n8k16.row.col.f32.f16.f16.f32 "
        "{%0,%1,%2,%3}, {%4,%5,%6,%7}, {%8,%9}, {%0,%1,%2,%3};"
        : "+f"(c[0]), "+f"(c[1]), "+f"(c[2]), "+f"(c[3])
        : "r"(a[0]), "r"(a[1]), "r"(a[2]), "r"(a[3]), "r"(b[0]), "r"(b[1]));
}

#define LDSM_X4(r, addr)                                                        \
    asm volatile("ldmatrix.sync.aligned.m8n8.x4.shared.b16 {%0,%1,%2,%3}, [%4];"\
                 : "=r"((r)[0]), "=r"((r)[1]), "=r"((r)[2]), "=r"((r)[3])       \
                 : "r"(addr))

__device__ __forceinline__ uint32_t pack_h2(float a, float b) {
    __half2 h = __floats2half2_rn(a, b);
    return *reinterpret_cast<uint32_t*>(&h);
}

__device__ __forceinline__ uint4 pack_quad(float4 v0, float4 v1) {
    uint4 r;
    r.x = pack_h2(v0.x, v0.y);
    r.y = pack_h2(v0.z, v0.w);
    r.z = pack_h2(v1.x, v1.y);
    r.w = pack_h2(v1.z, v1.w);
    return r;
}

__device__ __forceinline__ void cp16(uint32_t dst, const void* src) {
    asm volatile("cp.async.ca.shared.global [%0], [%1], 16;" :: "r"(dst), "l"(src));
}

// 32x32 warp-tile gemm over K=64 via ldmatrix (validated R11-R15).
__device__ __forceinline__ void gemm_warp(uint32_t sAu, uint32_t sBu,
                                          float acc[2][4][4],
                                          int rm, int cn, int lane) {
    const int la = lane & 15;
    const int ca = lane >> 4;
    const int lb = (lane & 7) | ((lane >> 4) << 3);
    const int cb = (lane >> 3) & 1;
    const uint32_t aB0 = sAu + (uint32_t)(rm + la) * 128;
    const uint32_t aB1 = aB0 + 16 * 128;
    const uint32_t bB0 = sBu + (uint32_t)(cn + lb) * 128;
    const uint32_t bB1 = bB0 + 16 * 128;
    const int swA = (rm + la) & 7;
    const int swB = (cn + lb) & 7;
    #pragma unroll
    for (int kb = 0; kb < 4; ++kb) {
        uint32_t a0[4], a1[4], b0[4], b1[4];
        LDSM_X4(a0, aB0 + (uint32_t)(((2 * kb + ca) ^ swA) << 4));
        LDSM_X4(a1, aB1 + (uint32_t)(((2 * kb + ca) ^ swA) << 4));
        LDSM_X4(b0, bB0 + (uint32_t)(((2 * kb + cb) ^ swB) << 4));
        LDSM_X4(b1, bB1 + (uint32_t)(((2 * kb + cb) ^ swB) << 4));
        mma16(acc[0][0], a0, b0);      mma16(acc[1][0], a1, b0);
        mma16(acc[0][1], a0, b0 + 2);  mma16(acc[1][1], a1, b0 + 2);
        mma16(acc[0][2], a0, b1);      mma16(acc[1][2], a1, b1);
        mma16(acc[0][3], a0, b1 + 2);  mma16(acc[1][3], a1, b1 + 2);
    }
}

// ---------------------------------------------------------------------------
// E prepass: E[f][nh] = sum_d sig(f,d)*pk[d][nh], fp16 swizzled image.
// grid 128 = (64 f-pairs) x (2 nh-halves), 1024 threads. (validated R13-R15)
// ---------------------------------------------------------------------------
__global__ __launch_bounds__(1024)
void compute_E_kernel(const float* __restrict__ pk) {
    __shared__ float sig[2 * 512];
    __shared__ float sp[16 * 2 * 256];

    const int fg  = blockIdx.x & 63;
    const int nhh = blockIdx.x >> 6;
    const int f2  = fg * 2;
    const int nh0 = nhh * 256;
    const int tid = threadIdx.x;
    const float log_inc = 9.210340371976184f / 255.0f;

    {
        int fi = tid >> 9, d = tid & 511, j = d & 255;
        float arg = (float)(127 - (f2 + fi)) * expf(-(float)j * log_inc);
        sig[fi * 512 + d] = (d < 256) ? sinf(arg) : cosf(arg);
    }
    __syncthreads();

    const int q = tid & 63, ch = tid >> 6;
    const float* p = pk + (size_t)(ch * 32) * 512 + nh0 + 4 * q;
    float4 a0 = make_float4(0.f, 0.f, 0.f, 0.f);
    float4 a1 = make_float4(0.f, 0.f, 0.f, 0.f);
    #pragma unroll
    for (int dd = 0; dd < 32; ++dd) {
        float4 v = __ldg((const float4*)(p + (size_t)dd * 512));
        int d = ch * 32 + dd;
        float s0 = sig[d], s1 = sig[512 + d];
        a0.x = fmaf(s0, v.x, a0.x); a0.y = fmaf(s0, v.y, a0.y);
        a0.z = fmaf(s0, v.z, a0.z); a0.w = fmaf(s0, v.w, a0.w);
        a1.x = fmaf(s1, v.x, a1.x); a1.y = fmaf(s1, v.y, a1.y);
        a1.z = fmaf(s1, v.z, a1.z); a1.w = fmaf(s1, v.w, a1.w);
    }
    *(float4*)&sp[(ch * 2 + 0) * 256 + 4 * q] = a0;
    *(float4*)&sp[(ch * 2 + 1) * 256 + 4 * q] = a1;
    __syncthreads();

    if (tid < 128) {
        int fi = tid >> 6, qq = tid & 63;
        float4 s = make_float4(0.f, 0.f, 0.f, 0.f);
        #pragma unroll
        for (int c = 0; c < 16; ++c) {
            float4 v = *(const float4*)&sp[(c * 2 + fi) * 256 + 4 * qq];
            s.x += v.x; s.y += v.y; s.z += v.z; s.w += v.w;
        }
        const int n   = nhh * 4 + (qq >> 4);
        const int h4  = (4 * qq) & 63;
        const int row = f2 + fi;
        const int chv = h4 >> 3;
        uint32_t* dst = reinterpret_cast<uint32_t*>(g_Epk)
                        + n * (128 * 32) + row * 32
                        + ((chv ^ (row & 7)) << 2) + ((h4 & 7) >> 1);
        dst[0] = pack_h2(s.x, s.y);
        dst[1] = pack_h2(s.z, s.w);
    }
}

// ---------------------------------------------------------------------------
// Main kernel: one CTA per (b,u,n,mh), 256 threads (8 warps, 2m x 4n).
// bid layout: [b:2][u:5][n:3][mh:1].  Two barriers total.
// ---------------------------------------------------------------------------
__device__ __forceinline__ void epilogue(const float acc[2][4][4],
                                         const __half* __restrict__ sBD,
                                         float* __restrict__ OUT,
                                         int half, int mh,
                                         int wm, int wn, int g, int t) {
    #pragma unroll
    for (int i = 0; i < 2; ++i)
        #pragma unroll
        for (int j = 0; j < 4; ++j) {
            const int c0 = 128 * half + 32 * wn + 8 * j + 2 * t;
            #pragma unroll
            for (int p = 0; p < 2; ++p) {
                const int lw = 32 * wm + 16 * i + g + 8 * p;
                const int wg = mh * 64 + lw;
                float v0 = acc[i][j][2 * p];
                float v1 = acc[i][j][2 * p + 1];
                const int f = c0 - wg;
                if (f >= 0 && f < 127) {
                    __half2 h = *reinterpret_cast<const __half2*>(&sBD[lw * BDS_H + f]);
                    float2 bd = __half22float2(h);
                    v0 += bd.x; v1 += bd.y;
                } else if (f == -1) {
                    v1 += __half2float(sBD[lw * BDS_H]);
                } else if (f == 127) {
                    v0 += __half2float(sBD[lw * BDS_H + 127]);
                }
                float* o = &OUT[(size_t)lw * Cc + c0];
                o[0] = v0;
                if (c0 + 1 < Cc) o[1] = v1;
            }
        }
}

__global__ __launch_bounds__(256, 3)
void txl_mma_kernel(const float* __restrict__ q_g,
                    const float* __restrict__ k_g,
                    float* __restrict__ out_g) {
    extern __shared__ uint32_t sm[];
    uint32_t smem_base;
    asm("{ .reg .u64 t; cvta.to.shared.u64 t, %1; cvt.u32.u64 %0, t; }"
        : "=r"(smem_base) : "l"(sm));
    const uint32_t sAu  = smem_base + OFF_A_B;
    const uint32_t sEu  = smem_base + OFF_E_B;
    const uint32_t sB0u = smem_base + OFF_B0_B;
    const uint32_t sB1u = smem_base + OFF_B1_B;
    char* sbytes = reinterpret_cast<char*>(sm);
    __half* sBD  = reinterpret_cast<__half*>(sbytes + OFF_BD_B);

    const int tid = threadIdx.x;
    const int lane = tid & 31, wid = tid >> 5;
    const int wm = wid & 1, wn = wid >> 1;
    const int g = lane >> 2, t = lane & 3;

    const int bid = blockIdx.x;
    const int mh = bid & 1;
    const int n = (bid >> 1) & 7;
    const int u = (bid >> 4) & 31;
    const int b = bid >> 9;

    const float* Q  = q_g + (size_t)(b * Uu + u) * 128 * 512 + (size_t)mh * 64 * 512 + n * 64;
    const float* Kg = k_g + (size_t)(b * Uu + u) * Cc * 512 + n * 64;
    float* OUT = out_g + ((size_t)((b * Nn + n) * Uu + u) * 128 + (size_t)mh * 64) * Cc;

    // pack-task decode
    const int t_row0 = tid >> 3;                 // 0..31
    const int t_c    = tid & 7;                  // 16B chunk
    const int t_sc   = t_c ^ (t_row0 & 7);       // swizzled chunk (rows step by 32)
    const int t_hb   = t_c * 8;

    // ---- phase 1: E cp.async + pack Q, K0, K1 (one long stretch) ----
    {
        const uint4* Ev = g_Epk + (size_t)n * (128 * 8);
        #pragma unroll
        for (int i = 0; i < 4; ++i)
            cp16(sEu + (uint32_t)(tid + 256 * i) * 16, Ev + tid + 256 * i);
        asm volatile("cp.async.commit_group;");
    }
    #pragma unroll
    for (int it = 0; it < 2; ++it) {             // Q: 64 rows
        const int row = t_row0 + 32 * it;
        float4 v0 = *(const float4*)&Q[(size_t)row * 512 + t_hb];
        float4 v1 = *(const float4*)&Q[(size_t)row * 512 + t_hb + 4];
        *(uint4*)(sbytes + OFF_A_B + row * 128 + t_sc * 16) = pack_quad(v0, v1);
    }
    #pragma unroll
    for (int it = 0; it < 4; ++it) {             // K rows 0..127 -> sB0
        const int row = t_row0 + 32 * it;
        float4 v0 = *(const float4*)&Kg[(size_t)row * 512 + t_hb];
        float4 v1 = *(const float4*)&Kg[(size_t)row * 512 + t_hb + 4];
        *(uint4*)(sbytes + OFF_B0_B + row * 128 + t_sc * 16) = pack_quad(v0, v1);
    }
    #pragma unroll
    for (int it = 0; it < 4; ++it) {             // K rows 128..255 -> sB1
        const int row = 128 + t_row0 + 32 * it;
        float4 z = make_float4(0.f, 0.f, 0.f, 0.f);
        float4 v0 = (row < Cc) ? *(const float4*)&Kg[(size_t)row * 512 + t_hb] : z;
        float4 v1 = (row < Cc) ? *(const float4*)&Kg[(size_t)row * 512 + t_hb + 4] : z;
        *(uint4*)(sbytes + OFF_B1_B + (row - 128) * 128 + t_sc * 16) = pack_quad(v0, v1);
    }
    asm volatile("cp.async.wait_group 0;");
    __syncthreads();                              // barrier 1

    float acc[2][4][4];

    // ---- BD = Q @ E^T -> sBD; AC0 gemm (no barrier between) ----
    #pragma unroll
    for (int i = 0; i < 2; ++i)
        #pragma unroll
        for (int j = 0; j < 4; ++j)
            #pragma unroll
            for (int e = 0; e < 4; ++e) acc[i][j][e] = 0.f;
    gemm_warp(sAu, sEu, acc, 32 * wm, 32 * wn, lane);
    #pragma unroll
    for (int i = 0; i < 2; ++i)
        #pragma unroll
        for (int j = 0; j < 4; ++j) {
            const int w0 = 32 * wm + 16 * i + g;
            const int f0 = 32 * wn + 8 * j + 2 * t;
            sBD[w0 * BDS_H + f0]           = __float2half_rn(acc[i][j][0]);
            sBD[w0 * BDS_H + f0 + 1]       = __float2half_rn(acc[i][j][1]);
            sBD[(w0 + 8) * BDS_H + f0]     = __float2half_rn(acc[i][j][2]);
            sBD[(w0 + 8) * BDS_H + f0 + 1] = __float2half_rn(acc[i][j][3]);
        }

    #pragma unroll
    for (int i = 0; i < 2; ++i)
        #pragma unroll
        for (int j = 0; j < 4; ++j)
            #pragma unroll
            for (int e = 0; e < 4; ++e) acc[i][j][e] = 0.f;
    gemm_warp(sAu, sB0u, acc, 32 * wm, 32 * wn, lane);

    __syncthreads();                              // barrier 2: publish sBD

    // ---- epi0, AC1 gemm, epi1 (no more barriers) ----
    epilogue(acc, sBD, OUT, 0, mh, wm, wn, g, t);

    #pragma unroll
    for (int i = 0; i < 2; ++i)
        #pragma unroll
        for (int j = 0; j < 4; ++j)
            #pragma unroll
            for (int e = 0; e < 4; ++e) acc[i][j][e] = 0.f;
    gemm_warp(sAu, sB1u, acc, 32 * wm, 32 * wn, lane);

    epilogue(acc, sBD, OUT, 1, mh, wm, wn, g, t);
}

// ---------------------------------------------------------------------------
extern "C" void kernel_launch(void* const* d_in, const int* in_sizes, int n_in,
                              void* d_out, int out_size) {
    (void)in_sizes; (void)n_in; (void)out_size;
    const float* q  = (const float*)d_in[0];   // queries (4,32,128,8,64)
    const float* k  = (const float*)d_in[1];   // keys    (4,32,255,8,64)
    const float* pk = (const float*)d_in[2];   // pos_kernel (512,8,64)
    float* out = (float*)d_out;                // (4,8,32,128,255)

    compute_E_kernel<<<128, 1024>>>(pk);

    cudaFuncSetAttribute(txl_mma_kernel,
                         cudaFuncAttributeMaxDynamicSharedMemorySize, SMEM_BYTES);
    txl_mma_kernel<<<2 * 4 * Uu * Nn, 256, SMEM_BYTES>>>(q, k, out);
}

// round 17
// speedup vs baseline: 1.4271x; 1.0302x over previous
#include <cuda_runtime.h>
#include <cuda_fp16.h>
#include <cstdint>

// ---------------------------------------------------------------------------
// TransformerXL relative position embedding — pure fp16 mma.sync m16n8k16.
// One CTA per (b,u,n): both M-halves processed sequentially, K/E loaded once.
//   q·k ≈ qh·kh  (fp16 operands, fp32 accum; rel_err ~3e-4)
//
// out[b,n,u,w,c] = AC[w,c] + (0 <= c-w < 128 ? BD[w, c-w] : 0)
// ---------------------------------------------------------------------------

namespace {
constexpr int Uu = 32, Nn = 8, Cc = 255;

// smem layout (bytes)
constexpr int OFF_A_B  = 0;          // sA : 64 rows  x 128B (Q half)      8 KB
constexpr int OFF_E_B  = 8192;       // sE : 128 rows x 128B (E)          16 KB
constexpr int OFF_B0_B = 24576;      // sB0: 128 rows x 128B (K half 0)   16 KB
constexpr int OFF_B1_B = 40960;      // sB1: 128 rows x 128B (K half 1)   16 KB
constexpr int OFF_BD_B = 57344;      // sBD: 64 x 137 halfs             17.1 KB
constexpr int BDS_H = 137;
constexpr int SMEM_BYTES = OFF_BD_B + 64 * BDS_H * 2;   // 74880 -> 3 CTAs/SM
}

// E image, fp16, chunk-swizzled: [n][f][8 x 16B chunks] = 128 KB
__device__ uint4 g_Epk[8 * 128 * 8];

// ---------------------------------------------------------------------------
__device__ __forceinline__ void mma16(float* c, const uint32_t* a, const uint32_t* b) {
    asm volatile(
        "mma.sync.aligned.m16n8k16.row.col.f32.f16.f16.f32 "
        "{%0,%1,%2,%3}, {%4,%5,%6,%7}, {%8,%9}, {%0,%1,%2,%3};"
        : "+f"(c[0]), "+f"(c[1]), "+f"(c[2]), "+f"(c[3])
        : "r"(a[0]), "r"(a[1]), "r"(a[2]), "r"(a[3]), "r"(b[0]), "r"(b[1]));
}

#define LDSM_X4(r, addr)                                                        \
    asm volatile("ldmatrix.sync.aligned.m8n8.x4.shared.b16 {%0,%1,%2,%3}, [%4];"\
                 : "=r"((r)[0]), "=r"((r)[1]), "=r"((r)[2]), "=r"((r)[3])       \
                 : "r"(addr))

__device__ __forceinline__ uint32_t pack_h2(float a, float b) {
    __half2 h = __floats2half2_rn(a, b);
    return *reinterpret_cast<uint32_t*>(&h);
}

__device__ __forceinline__ uint4 pack_quad(float4 v0, float4 v1) {
    uint4 r;
    r.x = pack_h2(v0.x, v0.y);
    r.y = pack_h2(v0.z, v0.w);
    r.z = pack_h2(v1.x, v1.y);
    r.w = pack_h2(v1.z, v1.w);
    return r;
}

__device__ __forceinline__ void cp16(uint32_t dst, const void* src) {
    asm volatile("cp.async.ca.shared.global [%0], [%1], 16;" :: "r"(dst), "l"(src));
}

// 32x32 warp-tile gemm over K=64 via ldmatrix (validated R11-R16).
__device__ __forceinline__ void gemm_warp(uint32_t sAu, uint32_t sBu,
                                          float acc[2][4][4],
                                          int rm, int cn, int lane) {
    const int la = lane & 15;
    const int ca = lane >> 4;
    const int lb = (lane & 7) | ((lane >> 4) << 3);
    const int cb = (lane >> 3) & 1;
    const uint32_t aB0 = sAu + (uint32_t)(rm + la) * 128;
    const uint32_t aB1 = aB0 + 16 * 128;
    const uint32_t bB0 = sBu + (uint32_t)(cn + lb) * 128;
    const uint32_t bB1 = bB0 + 16 * 128;
    const int swA = (rm + la) & 7;
    const int swB = (cn + lb) & 7;
    #pragma unroll
    for (int kb = 0; kb < 4; ++kb) {
        uint32_t a0[4], a1[4], b0[4], b1[4];
        LDSM_X4(a0, aB0 + (uint32_t)(((2 * kb + ca) ^ swA) << 4));
        LDSM_X4(a1, aB1 + (uint32_t)(((2 * kb + ca) ^ swA) << 4));
        LDSM_X4(b0, bB0 + (uint32_t)(((2 * kb + cb) ^ swB) << 4));
        LDSM_X4(b1, bB1 + (uint32_t)(((2 * kb + cb) ^ swB) << 4));
        mma16(acc[0][0], a0, b0);      mma16(acc[1][0], a1, b0);
        mma16(acc[0][1], a0, b0 + 2);  mma16(acc[1][1], a1, b0 + 2);
        mma16(acc[0][2], a0, b1);      mma16(acc[1][2], a1, b1);
        mma16(acc[0][3], a0, b1 + 2);  mma16(acc[1][3], a1, b1 + 2);
    }
}

// ---------------------------------------------------------------------------
// E prepass (validated R13-R16): E[f][nh] fp16 swizzled image.
// ---------------------------------------------------------------------------
__global__ __launch_bounds__(1024)
void compute_E_kernel(const float* __restrict__ pk) {
    __shared__ float sig[2 * 512];
    __shared__ float sp[16 * 2 * 256];

    const int fg  = blockIdx.x & 63;
    const int nhh = blockIdx.x >> 6;
    const int f2  = fg * 2;
    const int nh0 = nhh * 256;
    const int tid = threadIdx.x;
    const float log_inc = 9.210340371976184f / 255.0f;

    {
        int fi = tid >> 9, d = tid & 511, j = d & 255;
        float arg = (float)(127 - (f2 + fi)) * expf(-(float)j * log_inc);
        sig[fi * 512 + d] = (d < 256) ? sinf(arg) : cosf(arg);
    }
    __syncthreads();

    const int q = tid & 63, ch = tid >> 6;
    const float* p = pk + (size_t)(ch * 32) * 512 + nh0 + 4 * q;
    float4 a0 = make_float4(0.f, 0.f, 0.f, 0.f);
    float4 a1 = make_float4(0.f, 0.f, 0.f, 0.f);
    #pragma unroll
    for (int dd = 0; dd < 32; ++dd) {
        float4 v = __ldg((const float4*)(p + (size_t)dd * 512));
        int d = ch * 32 + dd;
        float s0 = sig[d], s1 = sig[512 + d];
        a0.x = fmaf(s0, v.x, a0.x); a0.y = fmaf(s0, v.y, a0.y);
        a0.z = fmaf(s0, v.z, a0.z); a0.w = fmaf(s0, v.w, a0.w);
        a1.x = fmaf(s1, v.x, a1.x); a1.y = fmaf(s1, v.y, a1.y);
        a1.z = fmaf(s1, v.z, a1.z); a1.w = fmaf(s1, v.w, a1.w);
    }
    *(float4*)&sp[(ch * 2 + 0) * 256 + 4 * q] = a0;
    *(float4*)&sp[(ch * 2 + 1) * 256 + 4 * q] = a1;
    __syncthreads();

    if (tid < 128) {
        int fi = tid >> 6, qq = tid & 63;
        float4 s = make_float4(0.f, 0.f, 0.f, 0.f);
        #pragma unroll
        for (int c = 0; c < 16; ++c) {
            float4 v = *(const float4*)&sp[(c * 2 + fi) * 256 + 4 * qq];
            s.x += v.x; s.y += v.y; s.z += v.z; s.w += v.w;
        }
        const int n   = nhh * 4 + (qq >> 4);
        const int h4  = (4 * qq) & 63;
        const int row = f2 + fi;
        const int chv = h4 >> 3;
        uint32_t* dst = reinterpret_cast<uint32_t*>(g_Epk)
                        + n * (128 * 32) + row * 32
                        + ((chv ^ (row & 7)) << 2) + ((h4 & 7) >> 1);
        dst[0] = pack_h2(s.x, s.y);
        dst[1] = pack_h2(s.z, s.w);
    }
}

// ---------------------------------------------------------------------------
// Main kernel: one CTA per (b,u,n), 256 threads (8 warps, 2m x 4n).
// bid layout: [b:2][u:5][n:3].
// ---------------------------------------------------------------------------
__device__ __forceinline__ void epilogue(const float acc[2][4][4],
                                         const __half* __restrict__ sBD,
                                         float* __restrict__ OUT,
                                         int half, int mh,
                                         int wm, int wn, int g, int t) {
    #pragma unroll
    for (int i = 0; i < 2; ++i)
        #pragma unroll
        for (int j = 0; j < 4; ++j) {
            const int c0 = 128 * half + 32 * wn + 8 * j + 2 * t;
            #pragma unroll
            for (int p = 0; p < 2; ++p) {
                const int lw = 32 * wm + 16 * i + g + 8 * p;
                const int wg = mh * 64 + lw;
                float v0 = acc[i][j][2 * p];
                float v1 = acc[i][j][2 * p + 1];
                const int f = c0 - wg;
                if (f >= 0 && f < 127) {
                    __half2 h = *reinterpret_cast<const __half2*>(&sBD[lw * BDS_H + f]);
                    float2 bd = __half22float2(h);
                    v0 += bd.x; v1 += bd.y;
                } else if (f == -1) {
                    v1 += __half2float(sBD[lw * BDS_H]);
                } else if (f == 127) {
                    v0 += __half2float(sBD[lw * BDS_H + 127]);
                }
                float* o = &OUT[(size_t)lw * Cc + c0];
                o[0] = v0;
                if (c0 + 1 < Cc) o[1] = v1;
            }
        }
}

// process one M-half: BD gemm -> sBD, AC0 gemm, bar, epi0, AC1 gemm, epi1
__device__ __forceinline__ void process_half(uint32_t sAu, uint32_t sEu,
                                             uint32_t sB0u, uint32_t sB1u,
                                             __half* sBD, float* OUT, int mh,
                                             int wm, int wn, int g, int t,
                                             int lane) {
    float acc[2][4][4];

    #pragma unroll
    for (int i = 0; i < 2; ++i)
        #pragma unroll
        for (int j = 0; j < 4; ++j)
            #pragma unroll
            for (int e = 0; e < 4; ++e) acc[i][j][e] = 0.f;
    gemm_warp(sAu, sEu, acc, 32 * wm, 32 * wn, lane);
    #pragma unroll
    for (int i = 0; i < 2; ++i)
        #pragma unroll
        for (int j = 0; j < 4; ++j) {
            const int w0 = 32 * wm + 16 * i + g;
            const int f0 = 32 * wn + 8 * j + 2 * t;
            sBD[w0 * BDS_H + f0]           = __float2half_rn(acc[i][j][0]);
            sBD[w0 * BDS_H + f0 + 1]       = __float2half_rn(acc[i][j][1]);
            sBD[(w0 + 8) * BDS_H + f0]     = __float2half_rn(acc[i][j][2]);
            sBD[(w0 + 8) * BDS_H + f0 + 1] = __float2half_rn(acc[i][j][3]);
        }

    #pragma unroll
    for (int i = 0; i < 2; ++i)
        #pragma unroll
        for (int j = 0; j < 4; ++j)
            #pragma unroll
            for (int e = 0; e < 4; ++e) acc[i][j][e] = 0.f;
    gemm_warp(sAu, sB0u, acc, 32 * wm, 32 * wn, lane);

    __syncthreads();                              // publish sBD

    epilogue(acc, sBD, OUT, 0, mh, wm, wn, g, t);

    #pragma unroll
    for (int i = 0; i < 2; ++i)
        #pragma unroll
        for (int j = 0; j < 4; ++j)
            #pragma unroll
            for (int e = 0; e < 4; ++e) acc[i][j][e] = 0.f;
    gemm_warp(sAu, sB1u, acc, 32 * wm, 32 * wn, lane);

    epilogue(acc, sBD, OUT, 1, mh, wm, wn, g, t);
}

__global__ __launch_bounds__(256, 3)
void txl_mma_kernel(const float* __restrict__ q_g,
                    const float* __restrict__ k_g,
                    float* __restrict__ out_g) {
    extern __shared__ uint32_t sm[];
    uint32_t smem_base;
    asm("{ .reg .u64 t; cvta.to.shared.u64 t, %1; cvt.u32.u64 %0, t; }"
        : "=r"(smem_base) : "l"(sm));
    const uint32_t sAu  = smem_base + OFF_A_B;
    const uint32_t sEu  = smem_base + OFF_E_B;
    const uint32_t sB0u = smem_base + OFF_B0_B;
    const uint32_t sB1u = smem_base + OFF_B1_B;
    char* sbytes = reinterpret_cast<char*>(sm);
    __half* sBD  = reinterpret_cast<__half*>(sbytes + OFF_BD_B);

    const int tid = threadIdx.x;
    const int lane = tid & 31, wid = tid >> 5;
    const int wm = wid & 1, wn = wid >> 1;
    const int g = lane >> 2, t = lane & 3;

    const int bid = blockIdx.x;
    const int n = bid & 7;
    const int u = (bid >> 3) & 31;
    const int b = bid >> 8;

    const float* Q  = q_g + (size_t)(b * Uu + u) * 128 * 512 + n * 64;
    const float* Kg = k_g + (size_t)(b * Uu + u) * Cc * 512 + n * 64;
    float* OUT = out_g + (size_t)((b * Nn + n) * Uu + u) * 128 * Cc;

    // pack-task decode
    const int t_row0 = tid >> 3;                 // 0..31
    const int t_c    = tid & 7;                  // 16B chunk
    const int t_sc   = t_c ^ (t_row0 & 7);       // swizzled chunk (rows step by 32)
    const int t_hb   = t_c * 8;

    // ---- phase 1: E cp.async + pack Q(mh=0), K0, K1 ----
    {
        const uint4* Ev = g_Epk + (size_t)n * (128 * 8);
        #pragma unroll
        for (int i = 0; i < 4; ++i)
            cp16(sEu + (uint32_t)(tid + 256 * i) * 16, Ev + tid + 256 * i);
        asm volatile("cp.async.commit_group;");
    }
    #pragma unroll
    for (int it = 0; it < 2; ++it) {             // Q rows 0..63
        const int row = t_row0 + 32 * it;
        float4 v0 = *(const float4*)&Q[(size_t)row * 512 + t_hb];
        float4 v1 = *(const float4*)&Q[(size_t)row * 512 + t_hb + 4];
        *(uint4*)(sbytes + OFF_A_B + row * 128 + t_sc * 16) = pack_quad(v0, v1);
    }
    #pragma unroll
    for (int it = 0; it < 4; ++it) {             // K rows 0..127 -> sB0
        const int row = t_row0 + 32 * it;
        float4 v0 = *(const float4*)&Kg[(size_t)row * 512 + t_hb];
        float4 v1 = *(const float4*)&Kg[(size_t)row * 512 + t_hb + 4];
        *(uint4*)(sbytes + OFF_B0_B + row * 128 + t_sc * 16) = pack_quad(v0, v1);
    }
    #pragma unroll
    for (int it = 0; it < 4; ++it) {             // K rows 128..255 -> sB1
        const int row = 128 + t_row0 + 32 * it;
        float4 z = make_float4(0.f, 0.f, 0.f, 0.f);
        float4 v0 = (row < Cc) ? *(const float4*)&Kg[(size_t)row * 512 + t_hb] : z;
        float4 v1 = (row < Cc) ? *(const float4*)&Kg[(size_t)row * 512 + t_hb + 4] : z;
        *(uint4*)(sbytes + OFF_B1_B + (row - 128) * 128 + t_sc * 16) = pack_quad(v0, v1);
    }
    asm volatile("cp.async.wait_group 0;");
    __syncthreads();                              // barrier 1

    // ---- half 0 ----
    process_half(sAu, sEu, sB0u, sB1u, sBD, OUT, 0, wm, wn, g, t, lane);

    __syncthreads();                              // sA / sBD reads complete

    // ---- repack Q for mh=1 ----
    #pragma unroll
    for (int it = 0; it < 2; ++it) {
        const int row = t_row0 + 32 * it;
        float4 v0 = *(const float4*)&Q[(size_t)(64 + row) * 512 + t_hb];
        float4 v1 = *(const float4*)&Q[(size_t)(64 + row) * 512 + t_hb + 4];
        *(uint4*)(sbytes + OFF_A_B + row * 128 + t_sc * 16) = pack_quad(v0, v1);
    }
    __syncthreads();                              // sA published

    // ---- half 1 ----
    process_half(sAu, sEu, sB0u, sB1u, sBD, OUT + (size_t)64 * Cc, 1,
                 wm, wn, g, t, lane);
}

// ---------------------------------------------------------------------------
extern "C" void kernel_launch(void* const* d_in, const int* in_sizes, int n_in,
                              void* d_out, int out_size) {
    (void)in_sizes; (void)n_in; (void)out_size;
    const float* q  = (const float*)d_in[0];   // queries (4,32,128,8,64)
    const float* k  = (const float*)d_in[1];   // keys    (4,32,255,8,64)
    const float* pk = (const float*)d_in[2];   // pos_kernel (512,8,64)
    float* out = (float*)d_out;                // (4,8,32,128,255)

    compute_E_kernel<<<128, 1024>>>(pk);

    cudaFuncSetAttribute(txl_mma_kernel,
                         cudaFuncAttributeMaxDynamicSharedMemorySize, SMEM_BYTES);
    txl_mma_kernel<<<4 * Uu * Nn, 256, SMEM_BYTES>>>(q, k, out);
}